// round 2
// baseline (speedup 1.0000x reference)
#include <cuda_runtime.h>
#include <cuda_bf16.h>
#include <math.h>

// Problem constants
#define B_   64
#define T_   512
#define IN_  256
#define H_   1024
#define G3_  3072          // 3*H
#define M_   (B_*T_)       // 32768

#define NTILE   32         // columns of hg per GEMM unit
#define KC      128        // k-chunk per GEMM unit
#define NSPLIT  (H_/KC)    // 8 K-splits
#define NUNITS  ((G3_/NTILE)*NSPLIT)   // 96*8 = 768

// -------------------- scratch (device globals; no cudaMalloc allowed) ------
__device__ __align__(256) float g_xg[(size_t)M_ * G3_];    // input projections
__device__ __align__(256) float g_y0[(size_t)M_ * H_];     // layer-0 outputs
__device__ __align__(256) float g_part[NSPLIT * B_ * G3_]; // split-K partials
__device__ __align__(256) float g_h[2 * B_ * H_];          // ping-pong hidden

// software grid barrier state
__device__ unsigned g_bar_count = 0;
__device__ volatile unsigned g_bar_gen = 0;

__device__ __forceinline__ void grid_barrier()
{
    __syncthreads();
    __threadfence();
    if (threadIdx.x == 0) {
        unsigned gen = g_bar_gen;
        if (atomicAdd(&g_bar_count, 1u) == gridDim.x - 1) {
            g_bar_count = 0;
            __threadfence();
            g_bar_gen = gen + 1;
        } else {
            while (g_bar_gen == gen) { }
        }
    }
    __syncthreads();
}

// -------------------- generic 64x64-tile SGEMM for input projections -------
// C = A * W^T (+bias). A:[M x K], W:[3072 x K], C:[M x 3072], all row-major.
__global__ void __launch_bounds__(64)
gemm64_kernel(const float* __restrict__ A,
              const float* __restrict__ W,
              const float* __restrict__ bias,
              float* __restrict__ C,
              int M, int K)
{
    const int n0 = blockIdx.x * 64;
    const int m0 = blockIdx.z * 64;

    __shared__ float As[16][64];
    __shared__ float Ws[16][64];

    const int tid = threadIdx.x;
    const int tm = tid >> 3;
    const int tn = tid & 7;

    float acc[8][8];
#pragma unroll
    for (int i = 0; i < 8; i++)
#pragma unroll
        for (int j = 0; j < 8; j++) acc[i][j] = 0.f;

    for (int k0 = 0; k0 < K; k0 += 16) {
#pragma unroll
        for (int i = 0; i < 4; i++) {
            int q   = tid + 64 * i;
            int row = q >> 2;
            int kq  = (q & 3) * 4;
            float4 va = *(const float4*)(A + (size_t)(m0 + row) * K + k0 + kq);
            As[kq + 0][row] = va.x; As[kq + 1][row] = va.y;
            As[kq + 2][row] = va.z; As[kq + 3][row] = va.w;
            float4 vw = *(const float4*)(W + (size_t)(n0 + row) * K + k0 + kq);
            Ws[kq + 0][row] = vw.x; Ws[kq + 1][row] = vw.y;
            Ws[kq + 2][row] = vw.z; Ws[kq + 3][row] = vw.w;
        }
        __syncthreads();

#pragma unroll
        for (int kk = 0; kk < 16; kk++) {
            float4 a0 = *(const float4*)&As[kk][tm * 8];
            float4 a1 = *(const float4*)&As[kk][tm * 8 + 4];
            float4 b0 = *(const float4*)&Ws[kk][tn * 8];
            float4 b1 = *(const float4*)&Ws[kk][tn * 8 + 4];
            float a[8] = {a0.x, a0.y, a0.z, a0.w, a1.x, a1.y, a1.z, a1.w};
            float b[8] = {b0.x, b0.y, b0.z, b0.w, b1.x, b1.y, b1.z, b1.w};
#pragma unroll
            for (int i = 0; i < 8; i++)
#pragma unroll
                for (int j = 0; j < 8; j++)
                    acc[i][j] = fmaf(a[i], b[j], acc[i][j]);
        }
        __syncthreads();
    }

#pragma unroll
    for (int i = 0; i < 8; i++) {
        int m = m0 + tm * 8 + i;
        float* crow = C + (size_t)m * G3_ + n0 + tn * 8;
        const float* bp = bias + n0 + tn * 8;
        float4 o0 = make_float4(acc[i][0] + bp[0], acc[i][1] + bp[1],
                                acc[i][2] + bp[2], acc[i][3] + bp[3]);
        float4 o1 = make_float4(acc[i][4] + bp[4], acc[i][5] + bp[5],
                                acc[i][6] + bp[6], acc[i][7] + bp[7]);
        *(float4*)(crow)     = o0;
        *(float4*)(crow + 4) = o1;
    }
}

// -------------------- persistent GRU recurrence kernel ---------------------
// One launch runs all T_ timesteps of one layer.
// Grid must be fully resident: grid = 2 * numSMs, 128 thr, 48KB smem.
__global__ void __launch_bounds__(128, 2)
gru_rec_kernel(const float* __restrict__ W_hh,
               const float* __restrict__ b_hh,
               const float* __restrict__ xg,
               float* __restrict__ part,
               float* __restrict__ h,      // [2][B_][H_] ping-pong
               float* __restrict__ y)      // [B_][T_][H_] or nullptr
{
    __shared__ float hs[KC][64];      // [k][row]   32 KB
    __shared__ float ws[KC][NTILE];   // [k][col]   16 KB

    const int cta  = blockIdx.x;
    const int ncta = gridDim.x;
    const int tid  = threadIdx.x;

    // zero initial hidden state (buffer 0)
    for (int i = cta * 128 + tid; i < B_ * H_; i += ncta * 128)
        h[i] = 0.f;
    grid_barrier();

    const int ty = tid >> 4;          // 0..7  -> rows ty*8..+7
    const int tx = tid & 15;          // 0..15 -> cols tx*2..+1
    const int r0 = ty * 8;
    const int c0 = tx * 2;

    for (int t = 0; t < T_; t++) {
        const float* hin = h + (t & 1) * (B_ * H_);
        float* hout      = h + ((t + 1) & 1) * (B_ * H_);

        // ---- split-K GEMM: part[s][b][g] = sum_{k in chunk s} h[b][k]*W_hh[g][k]
        for (int u = cta; u < NUNITS; u += ncta) {
            const int nt = u >> 3;           // 0..95
            const int kc = u & (NSPLIT - 1); // 0..7
            const int n0 = nt * NTILE;
            const int k0 = kc * KC;

            // load h tile transposed: hs[k][r]
            {
                int r    = tid & 63;
                int half = tid >> 6;          // 0..1, 64 k each
                const float* src = hin + (size_t)r * H_ + k0 + half * 64;
#pragma unroll
                for (int kk = 0; kk < 16; kk++) {
                    float4 v = __ldcg((const float4*)(src + kk * 4));
                    int k = half * 64 + kk * 4;
                    hs[k + 0][r] = v.x; hs[k + 1][r] = v.y;
                    hs[k + 2][r] = v.z; hs[k + 3][r] = v.w;
                }
            }
            // load W tile transposed: ws[k][c]
            {
                int c    = tid & 31;
                int half = tid >> 5;          // 0..3, 32 k each
                const float* src = W_hh + (size_t)(n0 + c) * H_ + k0 + half * 32;
#pragma unroll
                for (int kk = 0; kk < 8; kk++) {
                    float4 v = __ldg((const float4*)(src + kk * 4));
                    int k = half * 32 + kk * 4;
                    ws[k + 0][c] = v.x; ws[k + 1][c] = v.y;
                    ws[k + 2][c] = v.z; ws[k + 3][c] = v.w;
                }
            }
            __syncthreads();

            float acc[8][2];
#pragma unroll
            for (int i = 0; i < 8; i++) { acc[i][0] = 0.f; acc[i][1] = 0.f; }

#pragma unroll 4
            for (int k = 0; k < KC; k++) {
                float2 w  = *(const float2*)&ws[k][c0];
                float4 ha = *(const float4*)&hs[k][r0];
                float4 hb = *(const float4*)&hs[k][r0 + 4];
                float hv[8] = {ha.x, ha.y, ha.z, ha.w, hb.x, hb.y, hb.z, hb.w};
#pragma unroll
                for (int i = 0; i < 8; i++) {
                    acc[i][0] = fmaf(hv[i], w.x, acc[i][0]);
                    acc[i][1] = fmaf(hv[i], w.y, acc[i][1]);
                }
            }

            float* pbase = part + (size_t)(kc * B_) * G3_ + n0 + c0;
#pragma unroll
            for (int i = 0; i < 8; i++)
                *(float2*)(pbase + (size_t)(r0 + i) * G3_) =
                    make_float2(acc[i][0], acc[i][1]);
            __syncthreads();
        }
        grid_barrier();

        // ---- gate fusion: reduce partials, activations, update h
        for (int q = cta * 128 + tid; q < (B_ * H_) / 4; q += ncta * 128) {
            const int b  = q >> 8;            // H_/4 = 256 float4 per batch row
            const int jj = (q & 255) << 2;

            float4 hr = make_float4(0, 0, 0, 0);
            float4 hz = make_float4(0, 0, 0, 0);
            float4 hn = make_float4(0, 0, 0, 0);
#pragma unroll
            for (int s = 0; s < NSPLIT; s++) {
                const float* p = part + (size_t)(s * B_ + b) * G3_;
                float4 a = __ldcg((const float4*)(p + jj));
                float4 c = __ldcg((const float4*)(p + H_ + jj));
                float4 d = __ldcg((const float4*)(p + 2 * H_ + jj));
                hr.x += a.x; hr.y += a.y; hr.z += a.z; hr.w += a.w;
                hz.x += c.x; hz.y += c.y; hz.z += c.z; hz.w += c.w;
                hn.x += d.x; hn.y += d.y; hn.z += d.z; hn.w += d.w;
            }
            float4 br = *(const float4*)(b_hh + jj);
            float4 bz = *(const float4*)(b_hh + H_ + jj);
            float4 bn = *(const float4*)(b_hh + 2 * H_ + jj);

            const float* xgp = xg + ((size_t)b * T_ + t) * G3_;
            float4 xr = *(const float4*)(xgp + jj);
            float4 xz = *(const float4*)(xgp + H_ + jj);
            float4 xn = *(const float4*)(xgp + 2 * H_ + jj);

            float4 hp = __ldcg((const float4*)(hin + (size_t)b * H_ + jj));

            float hrv[4] = {hr.x + br.x, hr.y + br.y, hr.z + br.z, hr.w + br.w};
            float hzv[4] = {hz.x + bz.x, hz.y + bz.y, hz.z + bz.z, hz.w + bz.w};
            float hnv[4] = {hn.x + bn.x, hn.y + bn.y, hn.z + bn.z, hn.w + bn.w};
            float xrv[4] = {xr.x, xr.y, xr.z, xr.w};
            float xzv[4] = {xz.x, xz.y, xz.z, xz.w};
            float xnv[4] = {xn.x, xn.y, xn.z, xn.w};
            float hpv[4] = {hp.x, hp.y, hp.z, hp.w};

            float ho[4];
#pragma unroll
            for (int e = 0; e < 4; e++) {
                float r = 1.f / (1.f + expf(-(xrv[e] + hrv[e])));
                float z = 1.f / (1.f + expf(-(xzv[e] + hzv[e])));
                float n = tanhf(xnv[e] + r * hnv[e]);
                ho[e] = (1.f - z) * n + z * hpv[e];
            }
            float4 hw = make_float4(ho[0], ho[1], ho[2], ho[3]);
            *(float4*)(hout + (size_t)b * H_ + jj) = hw;
            if (y)
                *(float4*)(y + ((size_t)b * T_ + t) * H_ + jj) = hw;
        }
        grid_barrier();
    }
}

// -------------------- final fc ---------------------------------------------
__global__ void fc_kernel(const float* __restrict__ h,
                          const float* __restrict__ Wfc,
                          const float* __restrict__ bfc,
                          float* __restrict__ out)
{
    int b = blockIdx.x;
    float s = 0.f;
    for (int j = threadIdx.x; j < H_; j += blockDim.x)
        s += h[b * H_ + j] * Wfc[j];
    __shared__ float red[256];
    red[threadIdx.x] = s;
    __syncthreads();
    for (int o = 128; o > 0; o >>= 1) {
        if (threadIdx.x < o) red[threadIdx.x] += red[threadIdx.x + o];
        __syncthreads();
    }
    if (threadIdx.x == 0) out[b] = red[0] + bfc[0];
}

// -------------------- launch -----------------------------------------------
extern "C" void kernel_launch(void* const* d_in, const int* in_sizes, int n_in,
                              void* d_out, int out_size)
{
    const float* x     = (const float*)d_in[0];
    const float* W_ih0 = (const float*)d_in[1];
    const float* W_hh0 = (const float*)d_in[2];
    const float* b_ih0 = (const float*)d_in[3];
    const float* b_hh0 = (const float*)d_in[4];
    const float* W_ih1 = (const float*)d_in[5];
    const float* W_hh1 = (const float*)d_in[6];
    const float* b_ih1 = (const float*)d_in[7];
    const float* b_hh1 = (const float*)d_in[8];
    const float* W_fc  = (const float*)d_in[9];
    const float* b_fc  = (const float*)d_in[10];
    float* out = (float*)d_out;

    float *xg, *y0, *part, *h;
    cudaGetSymbolAddress((void**)&xg,   g_xg);
    cudaGetSymbolAddress((void**)&y0,   g_y0);
    cudaGetSymbolAddress((void**)&part, g_part);
    cudaGetSymbolAddress((void**)&h,    g_h);

    int numSM = 0, dev = 0;
    cudaGetDevice(&dev);
    cudaDeviceGetAttribute(&numSM, cudaDevAttrMultiProcessorCount, dev);
    const int recGrid = 2 * numSM;   // __launch_bounds__(128,2) guarantees residency

    const dim3 gXproj(G3_ / 64, 1, M_ / 64);

    // layer 0
    gemm64_kernel<<<gXproj, 64>>>(x, W_ih0, b_ih0, xg, M_, IN_);
    gru_rec_kernel<<<recGrid, 128>>>(W_hh0, b_hh0, xg, part, h, y0);

    // layer 1
    gemm64_kernel<<<gXproj, 64>>>(y0, W_ih1, b_ih1, xg, M_, H_);
    gru_rec_kernel<<<recGrid, 128>>>(W_hh1, b_hh1, xg, part, h, nullptr);

    // final hidden state is in buffer 0 (t=511 writes h[(511+1)&1] = buf0)
    fc_kernel<<<B_, 256>>>(h, W_fc, b_fc, out);
}

// round 3
// speedup vs baseline: 1.0002x; 1.0002x over previous
#include <cuda_runtime.h>
#include <cuda_bf16.h>
#include <math.h>

// Problem constants
#define B_   64
#define T_   512
#define IN_  256
#define H_   1024
#define G3_  3072          // 3*H
#define M_   (B_*T_)       // 32768

#define NTILE   32         // columns of hg per GEMM unit
#define KC      128        // k-chunk per GEMM unit
#define NSPLIT  (H_/KC)    // 8 K-splits
#define NUNITS  ((G3_/NTILE)*NSPLIT)   // 96*8 = 768

// -------------------- scratch (device globals; no cudaMalloc allowed) ------
__device__ __align__(256) float g_xg[(size_t)M_ * G3_];    // input projections
__device__ __align__(256) float g_y0[(size_t)M_ * H_];     // layer-0 outputs
__device__ __align__(256) float g_part[NSPLIT * B_ * G3_]; // split-K partials
__device__ __align__(256) float g_h[2 * B_ * H_];          // ping-pong hidden

// software grid barrier state
__device__ unsigned g_bar_count = 0;
__device__ volatile unsigned g_bar_gen = 0;

__device__ __forceinline__ void grid_barrier()
{
    __syncthreads();
    __threadfence();
    if (threadIdx.x == 0) {
        unsigned gen = g_bar_gen;
        if (atomicAdd(&g_bar_count, 1u) == gridDim.x - 1) {
            g_bar_count = 0;
            __threadfence();
            g_bar_gen = gen + 1;
        } else {
            while (g_bar_gen == gen) { }
        }
    }
    __syncthreads();
}

// -------------------- generic 64x64-tile SGEMM for input projections -------
// C = A * W^T (+bias). A:[M x K], W:[3072 x K], C:[M x 3072], all row-major.
__global__ void __launch_bounds__(64)
gemm64_kernel(const float* __restrict__ A,
              const float* __restrict__ W,
              const float* __restrict__ bias,
              float* __restrict__ C,
              int M, int K)
{
    const int n0 = blockIdx.x * 64;
    const int m0 = blockIdx.z * 64;

    __shared__ float As[16][64];
    __shared__ float Ws[16][64];

    const int tid = threadIdx.x;
    const int tm = tid >> 3;
    const int tn = tid & 7;

    float acc[8][8];
#pragma unroll
    for (int i = 0; i < 8; i++)
#pragma unroll
        for (int j = 0; j < 8; j++) acc[i][j] = 0.f;

    for (int k0 = 0; k0 < K; k0 += 16) {
#pragma unroll
        for (int i = 0; i < 4; i++) {
            int q   = tid + 64 * i;
            int row = q >> 2;
            int kq  = (q & 3) * 4;
            float4 va = *(const float4*)(A + (size_t)(m0 + row) * K + k0 + kq);
            As[kq + 0][row] = va.x; As[kq + 1][row] = va.y;
            As[kq + 2][row] = va.z; As[kq + 3][row] = va.w;
            float4 vw = *(const float4*)(W + (size_t)(n0 + row) * K + k0 + kq);
            Ws[kq + 0][row] = vw.x; Ws[kq + 1][row] = vw.y;
            Ws[kq + 2][row] = vw.z; Ws[kq + 3][row] = vw.w;
        }
        __syncthreads();

#pragma unroll
        for (int kk = 0; kk < 16; kk++) {
            float4 a0 = *(const float4*)&As[kk][tm * 8];
            float4 a1 = *(const float4*)&As[kk][tm * 8 + 4];
            float4 b0 = *(const float4*)&Ws[kk][tn * 8];
            float4 b1 = *(const float4*)&Ws[kk][tn * 8 + 4];
            float a[8] = {a0.x, a0.y, a0.z, a0.w, a1.x, a1.y, a1.z, a1.w};
            float b[8] = {b0.x, b0.y, b0.z, b0.w, b1.x, b1.y, b1.z, b1.w};
#pragma unroll
            for (int i = 0; i < 8; i++)
#pragma unroll
                for (int j = 0; j < 8; j++)
                    acc[i][j] = fmaf(a[i], b[j], acc[i][j]);
        }
        __syncthreads();
    }

#pragma unroll
    for (int i = 0; i < 8; i++) {
        int m = m0 + tm * 8 + i;
        float* crow = C + (size_t)m * G3_ + n0 + tn * 8;
        const float* bp = bias + n0 + tn * 8;
        float4 o0 = make_float4(acc[i][0] + bp[0], acc[i][1] + bp[1],
                                acc[i][2] + bp[2], acc[i][3] + bp[3]);
        float4 o1 = make_float4(acc[i][4] + bp[4], acc[i][5] + bp[5],
                                acc[i][6] + bp[6], acc[i][7] + bp[7]);
        *(float4*)(crow)     = o0;
        *(float4*)(crow + 4) = o1;
    }
}

// -------------------- persistent GRU recurrence kernel ---------------------
// One launch runs all T_ timesteps of one layer.
// Grid must be fully resident: grid = 2 * numSMs, 128 thr, 48KB smem.
__global__ void __launch_bounds__(128, 2)
gru_rec_kernel(const float* __restrict__ W_hh,
               const float* __restrict__ b_hh,
               const float* __restrict__ xg,
               float* __restrict__ part,
               float* __restrict__ h,      // [2][B_][H_] ping-pong
               float* __restrict__ y)      // [B_][T_][H_] or nullptr
{
    __shared__ float hs[KC][64];      // [k][row]   32 KB
    __shared__ float ws[KC][NTILE];   // [k][col]   16 KB

    const int cta  = blockIdx.x;
    const int ncta = gridDim.x;
    const int tid  = threadIdx.x;

    // zero initial hidden state (buffer 0)
    for (int i = cta * 128 + tid; i < B_ * H_; i += ncta * 128)
        h[i] = 0.f;
    grid_barrier();

    const int ty = tid >> 4;          // 0..7  -> rows ty*8..+7
    const int tx = tid & 15;          // 0..15 -> cols tx*2..+1
    const int r0 = ty * 8;
    const int c0 = tx * 2;

    for (int t = 0; t < T_; t++) {
        const float* hin = h + (t & 1) * (B_ * H_);
        float* hout      = h + ((t + 1) & 1) * (B_ * H_);

        // ---- split-K GEMM: part[s][b][g] = sum_{k in chunk s} h[b][k]*W_hh[g][k]
        for (int u = cta; u < NUNITS; u += ncta) {
            const int nt = u >> 3;           // 0..95
            const int kc = u & (NSPLIT - 1); // 0..7
            const int n0 = nt * NTILE;
            const int k0 = kc * KC;

            // load h tile transposed: hs[k][r]
            {
                int r    = tid & 63;
                int half = tid >> 6;          // 0..1, 64 k each
                const float* src = hin + (size_t)r * H_ + k0 + half * 64;
#pragma unroll
                for (int kk = 0; kk < 16; kk++) {
                    float4 v = __ldcg((const float4*)(src + kk * 4));
                    int k = half * 64 + kk * 4;
                    hs[k + 0][r] = v.x; hs[k + 1][r] = v.y;
                    hs[k + 2][r] = v.z; hs[k + 3][r] = v.w;
                }
            }
            // load W tile transposed: ws[k][c]
            {
                int c    = tid & 31;
                int half = tid >> 5;          // 0..3, 32 k each
                const float* src = W_hh + (size_t)(n0 + c) * H_ + k0 + half * 32;
#pragma unroll
                for (int kk = 0; kk < 8; kk++) {
                    float4 v = __ldg((const float4*)(src + kk * 4));
                    int k = half * 32 + kk * 4;
                    ws[k + 0][c] = v.x; ws[k + 1][c] = v.y;
                    ws[k + 2][c] = v.z; ws[k + 3][c] = v.w;
                }
            }
            __syncthreads();

            float acc[8][2];
#pragma unroll
            for (int i = 0; i < 8; i++) { acc[i][0] = 0.f; acc[i][1] = 0.f; }

#pragma unroll 4
            for (int k = 0; k < KC; k++) {
                float2 w  = *(const float2*)&ws[k][c0];
                float4 ha = *(const float4*)&hs[k][r0];
                float4 hb = *(const float4*)&hs[k][r0 + 4];
                float hv[8] = {ha.x, ha.y, ha.z, ha.w, hb.x, hb.y, hb.z, hb.w};
#pragma unroll
                for (int i = 0; i < 8; i++) {
                    acc[i][0] = fmaf(hv[i], w.x, acc[i][0]);
                    acc[i][1] = fmaf(hv[i], w.y, acc[i][1]);
                }
            }

            float* pbase = part + (size_t)(kc * B_) * G3_ + n0 + c0;
#pragma unroll
            for (int i = 0; i < 8; i++)
                *(float2*)(pbase + (size_t)(r0 + i) * G3_) =
                    make_float2(acc[i][0], acc[i][1]);
            __syncthreads();
        }
        grid_barrier();

        // ---- gate fusion: reduce partials, activations, update h
        for (int q = cta * 128 + tid; q < (B_ * H_) / 4; q += ncta * 128) {
            const int b  = q >> 8;            // H_/4 = 256 float4 per batch row
            const int jj = (q & 255) << 2;

            float4 hr = make_float4(0, 0, 0, 0);
            float4 hz = make_float4(0, 0, 0, 0);
            float4 hn = make_float4(0, 0, 0, 0);
#pragma unroll
            for (int s = 0; s < NSPLIT; s++) {
                const float* p = part + (size_t)(s * B_ + b) * G3_;
                float4 a = __ldcg((const float4*)(p + jj));
                float4 c = __ldcg((const float4*)(p + H_ + jj));
                float4 d = __ldcg((const float4*)(p + 2 * H_ + jj));
                hr.x += a.x; hr.y += a.y; hr.z += a.z; hr.w += a.w;
                hz.x += c.x; hz.y += c.y; hz.z += c.z; hz.w += c.w;
                hn.x += d.x; hn.y += d.y; hn.z += d.z; hn.w += d.w;
            }
            float4 br = *(const float4*)(b_hh + jj);
            float4 bz = *(const float4*)(b_hh + H_ + jj);
            float4 bn = *(const float4*)(b_hh + 2 * H_ + jj);

            const float* xgp = xg + ((size_t)b * T_ + t) * G3_;
            float4 xr = *(const float4*)(xgp + jj);
            float4 xz = *(const float4*)(xgp + H_ + jj);
            float4 xn = *(const float4*)(xgp + 2 * H_ + jj);

            float4 hp = __ldcg((const float4*)(hin + (size_t)b * H_ + jj));

            float hrv[4] = {hr.x + br.x, hr.y + br.y, hr.z + br.z, hr.w + br.w};
            float hzv[4] = {hz.x + bz.x, hz.y + bz.y, hz.z + bz.z, hz.w + bz.w};
            float hnv[4] = {hn.x + bn.x, hn.y + bn.y, hn.z + bn.z, hn.w + bn.w};
            float xrv[4] = {xr.x, xr.y, xr.z, xr.w};
            float xzv[4] = {xz.x, xz.y, xz.z, xz.w};
            float xnv[4] = {xn.x, xn.y, xn.z, xn.w};
            float hpv[4] = {hp.x, hp.y, hp.z, hp.w};

            float ho[4];
#pragma unroll
            for (int e = 0; e < 4; e++) {
                float r = 1.f / (1.f + expf(-(xrv[e] + hrv[e])));
                float z = 1.f / (1.f + expf(-(xzv[e] + hzv[e])));
                float n = tanhf(xnv[e] + r * hnv[e]);
                ho[e] = (1.f - z) * n + z * hpv[e];
            }
            float4 hw = make_float4(ho[0], ho[1], ho[2], ho[3]);
            *(float4*)(hout + (size_t)b * H_ + jj) = hw;
            if (y)
                *(float4*)(y + ((size_t)b * T_ + t) * H_ + jj) = hw;
        }
        grid_barrier();
    }
}

// -------------------- final fc ---------------------------------------------
__global__ void fc_kernel(const float* __restrict__ h,
                          const float* __restrict__ Wfc,
                          const float* __restrict__ bfc,
                          float* __restrict__ out)
{
    int b = blockIdx.x;
    float s = 0.f;
    for (int j = threadIdx.x; j < H_; j += blockDim.x)
        s += h[b * H_ + j] * Wfc[j];
    __shared__ float red[256];
    red[threadIdx.x] = s;
    __syncthreads();
    for (int o = 128; o > 0; o >>= 1) {
        if (threadIdx.x < o) red[threadIdx.x] += red[threadIdx.x + o];
        __syncthreads();
    }
    if (threadIdx.x == 0) out[b] = red[0] + bfc[0];
}

// -------------------- launch -----------------------------------------------
extern "C" void kernel_launch(void* const* d_in, const int* in_sizes, int n_in,
                              void* d_out, int out_size)
{
    const float* x     = (const float*)d_in[0];
    const float* W_ih0 = (const float*)d_in[1];
    const float* W_hh0 = (const float*)d_in[2];
    const float* b_ih0 = (const float*)d_in[3];
    const float* b_hh0 = (const float*)d_in[4];
    const float* W_ih1 = (const float*)d_in[5];
    const float* W_hh1 = (const float*)d_in[6];
    const float* b_ih1 = (const float*)d_in[7];
    const float* b_hh1 = (const float*)d_in[8];
    const float* W_fc  = (const float*)d_in[9];
    const float* b_fc  = (const float*)d_in[10];
    float* out = (float*)d_out;

    float *xg, *y0, *part, *h;
    cudaGetSymbolAddress((void**)&xg,   g_xg);
    cudaGetSymbolAddress((void**)&y0,   g_y0);
    cudaGetSymbolAddress((void**)&part, g_part);
    cudaGetSymbolAddress((void**)&h,    g_h);

    int numSM = 0, dev = 0;
    cudaGetDevice(&dev);
    cudaDeviceGetAttribute(&numSM, cudaDevAttrMultiProcessorCount, dev);
    const int recGrid = 2 * numSM;   // __launch_bounds__(128,2) guarantees residency

    const dim3 gXproj(G3_ / 64, 1, M_ / 64);

    // layer 0
    gemm64_kernel<<<gXproj, 64>>>(x, W_ih0, b_ih0, xg, M_, IN_);
    gru_rec_kernel<<<recGrid, 128>>>(W_hh0, b_hh0, xg, part, h, y0);

    // layer 1
    gemm64_kernel<<<gXproj, 64>>>(y0, W_ih1, b_ih1, xg, M_, H_);
    gru_rec_kernel<<<recGrid, 128>>>(W_hh1, b_hh1, xg, part, h, nullptr);

    // final hidden state is in buffer 0 (t=511 writes h[(511+1)&1] = buf0)
    fc_kernel<<<B_, 256>>>(h, W_fc, b_fc, out);
}

// round 4
// speedup vs baseline: 1.7718x; 1.7715x over previous
#include <cuda_runtime.h>
#include <cuda_bf16.h>
#include <math.h>

#define B_   64
#define T_   512
#define IN_  256
#define H_   1024
#define G3_  3072
#define M_   (B_*T_)
#define RECG 96

// -------- scratch --------
__device__ __align__(256) float         g_xg[(size_t)M_ * G3_];
__device__ __align__(256) __nv_bfloat16 g_xp[(size_t)M_ * (3*IN_)];
__device__ __align__(256) __nv_bfloat16 g_yp[(size_t)M_ * (3*H_)];
__device__ __align__(256) __nv_bfloat16 g_w0p[(size_t)G3_ * (3*IN_)];
__device__ __align__(256) __nv_bfloat16 g_w1p[(size_t)G3_ * (3*H_)];
__device__ __align__(256) __nv_bfloat16 g_wh0[(size_t)G3_ * (2*H_)];
__device__ __align__(256) __nv_bfloat16 g_wh1[(size_t)G3_ * (2*H_)];
__device__ __align__(256) __nv_bfloat16 g_hp[(size_t)B_ * (2*H_)];
__device__ __align__(256) float         g_hf[2 * B_ * H_];
__device__ __align__(256) float         g_hg[(size_t)B_ * G3_];

__device__ unsigned g_bar_count = 0;
__device__ volatile unsigned g_bar_gen = 0;

__device__ __forceinline__ void grid_barrier()
{
    __syncthreads();
    __threadfence();
    if (threadIdx.x == 0) {
        unsigned gen = g_bar_gen;
        if (atomicAdd(&g_bar_count, 1u) == gridDim.x - 1) {
            g_bar_count = 0; __threadfence(); g_bar_gen = gen + 1;
        } else { while (g_bar_gen == gen) { } }
    }
    __syncthreads();
}

__device__ __forceinline__ void mma_bf16(float* d, const unsigned* a, const unsigned* b)
{
    asm volatile(
        "mma.sync.aligned.m16n8k16.row.col.f32.bf16.bf16.f32 "
        "{%0,%1,%2,%3},{%4,%5,%6,%7},{%8,%9},{%0,%1,%2,%3};\n"
        : "+f"(d[0]), "+f"(d[1]), "+f"(d[2]), "+f"(d[3])
        : "r"(a[0]), "r"(a[1]), "r"(a[2]), "r"(a[3]), "r"(b[0]), "r"(b[1]));
}

// -------- pack kernels --------
__global__ void pack_a3(const float* __restrict__ s, __nv_bfloat16* __restrict__ d, int n, int K)
{   // A-side [hi|lo|hi]
    for (int i = blockIdx.x*blockDim.x+threadIdx.x; i < n; i += gridDim.x*blockDim.x) {
        int r = i / K, k = i % K;
        __nv_bfloat16 hi = __float2bfloat16(s[i]);
        __nv_bfloat16 lo = __float2bfloat16(s[i] - __bfloat162float(hi));
        size_t b = (size_t)r*(3*K);
        d[b+k] = hi; d[b+K+k] = lo; d[b+2*K+k] = hi;
    }
}
__global__ void pack_b3(const float* __restrict__ s, __nv_bfloat16* __restrict__ d, int n, int K)
{   // B-side [hi|hi|lo]
    for (int i = blockIdx.x*blockDim.x+threadIdx.x; i < n; i += gridDim.x*blockDim.x) {
        int r = i / K, k = i % K;
        __nv_bfloat16 hi = __float2bfloat16(s[i]);
        __nv_bfloat16 lo = __float2bfloat16(s[i] - __bfloat162float(hi));
        size_t b = (size_t)r*(3*K);
        d[b+k] = hi; d[b+K+k] = hi; d[b+2*K+k] = lo;
    }
}
__global__ void pack_w2(const float* __restrict__ s, __nv_bfloat16* __restrict__ d, int n)
{   // W_hh [hi|lo], K=1024
    for (int i = blockIdx.x*blockDim.x+threadIdx.x; i < n; i += gridDim.x*blockDim.x) {
        int r = i >> 10, k = i & 1023;
        __nv_bfloat16 hi = __float2bfloat16(s[i]);
        __nv_bfloat16 lo = __float2bfloat16(s[i] - __bfloat162float(hi));
        size_t b = (size_t)r*2048;
        d[b+k] = hi; d[b+1024+k] = lo;
    }
}

// -------- input-projection GEMM: C[M][3072] = A[M][K3] * Bm[3072][K3]^T + bias
__global__ void __launch_bounds__(256)
gemm_mma(const __nv_bfloat16* __restrict__ A, const __nv_bfloat16* __restrict__ Bm,
         const float* __restrict__ bias, float* __restrict__ C, int K3)
{
    __shared__ __nv_bfloat16 As[2][128][24];
    __shared__ __nv_bfloat16 Bs[2][64][24];
    const int n0 = blockIdx.x * 64, m0 = blockIdx.y * 128;
    const int tid = threadIdx.x, w = tid >> 5, lane = tid & 31;
    const int mw = w >> 1, nw = w & 1, g = lane >> 2, q = lane & 3;

    float acc[2][4][4];
#pragma unroll
    for (int i=0;i<2;i++) for (int j=0;j<4;j++) for (int e=0;e<4;e++) acc[i][j][e]=0.f;

    const int steps = K3 / 16;
    const int arow = tid >> 1, ah = tid & 1;
    const bool bl = tid < 128;
    uint4 ra, rb;
    ra = *(const uint4*)(A + (size_t)(m0+arow)*K3 + ah*8);
    if (bl) rb = *(const uint4*)(Bm + (size_t)(n0+arow)*K3 + ah*8);
    *(uint4*)&As[0][arow][ah*8] = ra;
    if (bl) *(uint4*)&Bs[0][arow][ah*8] = rb;
    __syncthreads();

    for (int c = 0; c < steps; c++) {
        if (c+1 < steps) {
            int kb = (c+1)*16;
            ra = *(const uint4*)(A + (size_t)(m0+arow)*K3 + kb + ah*8);
            if (bl) rb = *(const uint4*)(Bm + (size_t)(n0+arow)*K3 + kb + ah*8);
        }
        const int p = c & 1;
        unsigned bf[4][2];
#pragma unroll
        for (int j=0;j<4;j++) {
            int col = nw*32 + j*8 + g;
            bf[j][0] = *(const unsigned*)&Bs[p][col][q*2];
            bf[j][1] = *(const unsigned*)&Bs[p][col][q*2+8];
        }
#pragma unroll
        for (int i=0;i<2;i++) {
            int r = mw*32 + i*16 + g;
            unsigned a[4];
            a[0] = *(const unsigned*)&As[p][r][q*2];
            a[1] = *(const unsigned*)&As[p][r+8][q*2];
            a[2] = *(const unsigned*)&As[p][r][q*2+8];
            a[3] = *(const unsigned*)&As[p][r+8][q*2+8];
#pragma unroll
            for (int j=0;j<4;j++) mma_bf16(acc[i][j], a, bf[j]);
        }
        if (c+1 < steps) {
            *(uint4*)&As[(c+1)&1][arow][ah*8] = ra;
            if (bl) *(uint4*)&Bs[(c+1)&1][arow][ah*8] = rb;
            __syncthreads();
        }
    }
#pragma unroll
    for (int i=0;i<2;i++) {
        int row = m0 + mw*32 + i*16 + g;
#pragma unroll
        for (int j=0;j<4;j++) {
            int col = n0 + nw*32 + j*8 + q*2;
            float b0 = bias[col], b1 = bias[col+1];
            *(float2*)(C + (size_t)row*G3_ + col)     = make_float2(acc[i][j][0]+b0, acc[i][j][1]+b1);
            *(float2*)(C + (size_t)(row+8)*G3_ + col) = make_float2(acc[i][j][2]+b0, acc[i][j][3]+b1);
        }
    }
}

// -------- persistent recurrence --------
// smem chunk rows of 128 bf16 = 16 units of 8; XOR swizzle unit^(row&7)
#define SWI(r,c) ((r)*128 + (((((c)>>3)) ^ ((r)&7))<<3) + ((c)&7))

__global__ void __launch_bounds__(256, 1)
gru_rec(const __nv_bfloat16* __restrict__ Wp, const float* __restrict__ b_hh,
        const float* __restrict__ xg, __nv_bfloat16* __restrict__ hp,
        float* __restrict__ hf, float* __restrict__ hg,
        __nv_bfloat16* __restrict__ yp)
{
    extern __shared__ __nv_bfloat16 smb[];
    __nv_bfloat16* Abuf = smb;           // [2][64*128]
    __nv_bfloat16* Bbuf = smb + 16384;   // [2][32*128]

    const int cta = blockIdx.x, tid = threadIdx.x;
    const int lane = tid & 31, w = tid >> 5;
    const int mw = w >> 1, nw = w & 1, g = lane >> 2, q = lane & 3;
    const int n0 = cta * 32;

    for (int i = cta*256+tid; i < B_*H_; i += RECG*256) {
        ((unsigned*)hp)[i] = 0u;  hf[i] = 0.f;
    }
    grid_barrier();

    for (int t = 0; t < T_; t++) {
        // stage chunk 0
#pragma unroll
        for (int i2=0;i2<4;i2++) {
            int idx = tid + 256*i2, r = idx>>4, u = idx&15;
            uint4 v = __ldcg((const uint4*)(hp + (size_t)r*2048 + (u>>3)*1024 + (u&7)*8));
            *(uint4*)(Abuf + r*128 + ((u^(r&7))<<3)) = v;
        }
#pragma unroll
        for (int i2=0;i2<2;i2++) {
            int idx = tid + 256*i2, r = idx>>4, u = idx&15;
            uint4 v = __ldg((const uint4*)(Wp + (size_t)(n0+r)*2048 + (u>>3)*1024 + (u&7)*8));
            *(uint4*)(Bbuf + r*128 + ((u^(r&7))<<3)) = v;
        }
        __syncthreads();

        float acc[2][4];
#pragma unroll
        for (int j=0;j<2;j++) for (int e=0;e<4;e++) acc[j][e]=0.f;

        for (int c = 0; c < 16; c++) {
            uint4 pa[4], pb[2];
            if (c+1 < 16) {
                int kb = (c+1)*64;
#pragma unroll
                for (int i2=0;i2<4;i2++) {
                    int idx = tid + 256*i2, r = idx>>4, u = idx&15;
                    pa[i2] = __ldcg((const uint4*)(hp + (size_t)r*2048 + (u>>3)*1024 + kb + (u&7)*8));
                }
#pragma unroll
                for (int i2=0;i2<2;i2++) {
                    int idx = tid + 256*i2, r = idx>>4, u = idx&15;
                    pb[i2] = __ldg((const uint4*)(Wp + (size_t)(n0+r)*2048 + (u>>3)*1024 + kb + (u&7)*8));
                }
            }
            const __nv_bfloat16* Ab = Abuf + (c&1)*8192;
            const __nv_bfloat16* Bb = Bbuf + (c&1)*4096;
#pragma unroll
            for (int kk=0;kk<4;kk++) {
                const int cb = kk*16 + q*2, r = mw*16 + g;
                unsigned ah[4], al[4];
                ah[0] = *(const unsigned*)&Ab[SWI(r,   cb)];
                ah[1] = *(const unsigned*)&Ab[SWI(r+8, cb)];
                ah[2] = *(const unsigned*)&Ab[SWI(r,   cb+8)];
                ah[3] = *(const unsigned*)&Ab[SWI(r+8, cb+8)];
                al[0] = *(const unsigned*)&Ab[SWI(r,   cb+64)];
                al[1] = *(const unsigned*)&Ab[SWI(r+8, cb+64)];
                al[2] = *(const unsigned*)&Ab[SWI(r,   cb+72)];
                al[3] = *(const unsigned*)&Ab[SWI(r+8, cb+72)];
#pragma unroll
                for (int j=0;j<2;j++) {
                    const int nn = nw*16 + j*8 + g;
                    unsigned bh[2], blo[2];
                    bh[0]  = *(const unsigned*)&Bb[SWI(nn, cb)];
                    bh[1]  = *(const unsigned*)&Bb[SWI(nn, cb+8)];
                    blo[0] = *(const unsigned*)&Bb[SWI(nn, cb+64)];
                    blo[1] = *(const unsigned*)&Bb[SWI(nn, cb+72)];
                    mma_bf16(acc[j], ah, bh);
                    mma_bf16(acc[j], al, bh);
                    mma_bf16(acc[j], ah, blo);
                }
            }
            if (c+1 < 16) {
                __nv_bfloat16* Ad = Abuf + ((c+1)&1)*8192;
                __nv_bfloat16* Bd = Bbuf + ((c+1)&1)*4096;
#pragma unroll
                for (int i2=0;i2<4;i2++) {
                    int idx = tid + 256*i2, r = idx>>4, u = idx&15;
                    *(uint4*)(Ad + r*128 + ((u^(r&7))<<3)) = pa[i2];
                }
#pragma unroll
                for (int i2=0;i2<2;i2++) {
                    int idx = tid + 256*i2, r = idx>>4, u = idx&15;
                    *(uint4*)(Bd + r*128 + ((u^(r&7))<<3)) = pb[i2];
                }
                __syncthreads();
            }
        }

        // write hg tile
#pragma unroll
        for (int j=0;j<2;j++) {
            int row = mw*16 + g, col = n0 + nw*16 + j*8 + q*2;
            *(float2*)(hg + (size_t)row*G3_ + col)     = make_float2(acc[j][0], acc[j][1]);
            *(float2*)(hg + (size_t)(row+8)*G3_ + col) = make_float2(acc[j][2], acc[j][3]);
        }
        grid_barrier();

        // gates
        const float* hin = hf + (t&1)*(B_*H_);
        float* hout      = hf + ((t+1)&1)*(B_*H_);
        for (int e = cta*256+tid; e < B_*H_/2; e += RECG*256) {
            int b = e >> 9, jj = (e & 511) * 2;
            size_t gb = (size_t)b * G3_;
            float2 hr = __ldcg((const float2*)(hg + gb + jj));
            float2 hz = __ldcg((const float2*)(hg + gb + H_ + jj));
            float2 hn = __ldcg((const float2*)(hg + gb + 2*H_ + jj));
            const float* xp2 = xg + ((size_t)b*T_ + t)*G3_;
            float2 xr = *(const float2*)(xp2 + jj);
            float2 xz = *(const float2*)(xp2 + H_ + jj);
            float2 xn = *(const float2*)(xp2 + 2*H_ + jj);
            float2 br = *(const float2*)(b_hh + jj);
            float2 bz = *(const float2*)(b_hh + H_ + jj);
            float2 bn = *(const float2*)(b_hh + 2*H_ + jj);
            float2 hv = __ldcg((const float2*)(hin + (size_t)b*H_ + jj));
            float ho[2];
            float xrv[2]={xr.x,xr.y}, xzv[2]={xz.x,xz.y}, xnv[2]={xn.x,xn.y};
            float hrv[2]={hr.x+br.x,hr.y+br.y}, hzv[2]={hz.x+bz.x,hz.y+bz.y};
            float hnv[2]={hn.x+bn.x,hn.y+bn.y}, hpv[2]={hv.x,hv.y};
#pragma unroll
            for (int k=0;k<2;k++) {
                float r = 1.f/(1.f+expf(-(xrv[k]+hrv[k])));
                float z = 1.f/(1.f+expf(-(xzv[k]+hzv[k])));
                float n = tanhf(xnv[k] + r*hnv[k]);
                ho[k] = (1.f-z)*n + z*hpv[k];
            }
            *(float2*)(hout + (size_t)b*H_ + jj) = make_float2(ho[0], ho[1]);
            __nv_bfloat162 hi2, lo2;
            hi2.x = __float2bfloat16(ho[0]); hi2.y = __float2bfloat16(ho[1]);
            lo2.x = __float2bfloat16(ho[0]-__bfloat162float(hi2.x));
            lo2.y = __float2bfloat16(ho[1]-__bfloat162float(hi2.y));
            *(__nv_bfloat162*)(hp + (size_t)b*2048 + jj)        = hi2;
            *(__nv_bfloat162*)(hp + (size_t)b*2048 + 1024 + jj) = lo2;
            if (yp) {
                size_t yr = ((size_t)b*T_ + t) * 3072;
                *(__nv_bfloat162*)(yp + yr + jj)        = hi2;
                *(__nv_bfloat162*)(yp + yr + 1024 + jj) = lo2;
                *(__nv_bfloat162*)(yp + yr + 2048 + jj) = hi2;
            }
        }
        grid_barrier();
    }
}

// -------- final fc --------
__global__ void fc_kernel(const float* __restrict__ h, const float* __restrict__ Wfc,
                          const float* __restrict__ bfc, float* __restrict__ out)
{
    int b = blockIdx.x;
    float s = 0.f;
    for (int j = threadIdx.x; j < H_; j += blockDim.x) s += h[b*H_+j] * Wfc[j];
    __shared__ float red[256];
    red[threadIdx.x] = s; __syncthreads();
    for (int o = 128; o > 0; o >>= 1) {
        if (threadIdx.x < o) red[threadIdx.x] += red[threadIdx.x+o];
        __syncthreads();
    }
    if (threadIdx.x == 0) out[b] = red[0] + bfc[0];
}

// -------- launch --------
extern "C" void kernel_launch(void* const* d_in, const int* in_sizes, int n_in,
                              void* d_out, int out_size)
{
    const float* x     = (const float*)d_in[0];
    const float* W_ih0 = (const float*)d_in[1];
    const float* W_hh0 = (const float*)d_in[2];
    const float* b_ih0 = (const float*)d_in[3];
    const float* b_hh0 = (const float*)d_in[4];
    const float* W_ih1 = (const float*)d_in[5];
    const float* W_hh1 = (const float*)d_in[6];
    const float* b_ih1 = (const float*)d_in[7];
    const float* b_hh1 = (const float*)d_in[8];
    const float* W_fc  = (const float*)d_in[9];
    const float* b_fc  = (const float*)d_in[10];
    float* out = (float*)d_out;

    float *xg, *hf, *hg;
    __nv_bfloat16 *xp, *yp, *w0p, *w1p, *wh0, *wh1, *hp;
    cudaGetSymbolAddress((void**)&xg,  g_xg);
    cudaGetSymbolAddress((void**)&xp,  g_xp);
    cudaGetSymbolAddress((void**)&yp,  g_yp);
    cudaGetSymbolAddress((void**)&w0p, g_w0p);
    cudaGetSymbolAddress((void**)&w1p, g_w1p);
    cudaGetSymbolAddress((void**)&wh0, g_wh0);
    cudaGetSymbolAddress((void**)&wh1, g_wh1);
    cudaGetSymbolAddress((void**)&hp,  g_hp);
    cudaGetSymbolAddress((void**)&hf,  g_hf);
    cudaGetSymbolAddress((void**)&hg,  g_hg);

    pack_w2<<<512, 256>>>(W_hh0, wh0, G3_*H_);
    pack_w2<<<512, 256>>>(W_hh1, wh1, G3_*H_);
    pack_a3<<<512, 256>>>(x, xp, M_*IN_, IN_);
    pack_b3<<<512, 256>>>(W_ih0, w0p, G3_*IN_, IN_);
    pack_b3<<<512, 256>>>(W_ih1, w1p, G3_*H_, H_);

    gemm_mma<<<dim3(48, 256), 256>>>(xp, w0p, b_ih0, xg, 3*IN_);
    gru_rec<<<RECG, 256, 49152>>>(wh0, b_hh0, xg, hp, hf, hg, yp);
    gemm_mma<<<dim3(48, 256), 256>>>(yp, w1p, b_ih1, xg, 3*H_);
    gru_rec<<<RECG, 256, 49152>>>(wh1, b_hh1, xg, hp, hf, hg, nullptr);

    fc_kernel<<<B_, 256>>>(hf, W_fc, b_fc, out);  // h final in buffer 0
}

// round 5
// speedup vs baseline: 1.7966x; 1.0140x over previous
#include <cuda_runtime.h>
#include <cuda_bf16.h>
#include <math.h>

#define B_   64
#define T_   512
#define IN_  256
#define H_   1024
#define G3_  3072
#define M_   (B_*T_)
#define RECG 96

#define WSTR 2056    // W smem row stride (bf16): 1028 words, mod 32 = 4 -> conflict-free
#define ASTR 264     // A smem row stride (bf16): 132 words, mod 32 = 4
#define REC_SMEM ((32*WSTR + 2*64*ASTR) * 2)   // 199168 bytes

// -------- scratch --------
__device__ __align__(256) float         g_xg[(size_t)M_ * G3_];
__device__ __align__(256) __nv_bfloat16 g_xp[(size_t)M_ * (3*IN_)];
__device__ __align__(256) __nv_bfloat16 g_yp[(size_t)M_ * (3*H_)];
__device__ __align__(256) __nv_bfloat16 g_w0p[(size_t)G3_ * (3*IN_)];
__device__ __align__(256) __nv_bfloat16 g_w1p[(size_t)G3_ * (3*H_)];
__device__ __align__(256) __nv_bfloat16 g_wh0[(size_t)G3_ * (2*H_)];
__device__ __align__(256) __nv_bfloat16 g_wh1[(size_t)G3_ * (2*H_)];
__device__ __align__(256) __nv_bfloat16 g_hp[(size_t)B_ * (2*H_)];
__device__ __align__(256) float         g_hf[2 * B_ * H_];
__device__ __align__(256) float         g_hg[(size_t)B_ * G3_];

__device__ unsigned g_bar_count = 0;
__device__ volatile unsigned g_bar_gen = 0;

__device__ __forceinline__ void grid_barrier()
{
    __syncthreads();
    __threadfence();
    if (threadIdx.x == 0) {
        unsigned gen = g_bar_gen;
        if (atomicAdd(&g_bar_count, 1u) == gridDim.x - 1) {
            g_bar_count = 0; __threadfence(); g_bar_gen = gen + 1;
        } else { while (g_bar_gen == gen) { } }
    }
    __syncthreads();
}

__device__ __forceinline__ void mma_bf16(float* d, const unsigned* a, const unsigned* b)
{
    asm volatile(
        "mma.sync.aligned.m16n8k16.row.col.f32.bf16.bf16.f32 "
        "{%0,%1,%2,%3},{%4,%5,%6,%7},{%8,%9},{%0,%1,%2,%3};\n"
        : "+f"(d[0]), "+f"(d[1]), "+f"(d[2]), "+f"(d[3])
        : "r"(a[0]), "r"(a[1]), "r"(a[2]), "r"(a[3]), "r"(b[0]), "r"(b[1]));
}

// -------- pack helpers --------
__device__ __forceinline__ void packB3(const float* s, __nv_bfloat16* d, int n, int K,
                                       int tid0, int stride)
{   // B-side [hi|hi|lo]
    for (int i = tid0; i < n; i += stride) {
        int r = i / K, k = i % K;
        __nv_bfloat16 hi = __float2bfloat16(s[i]);
        __nv_bfloat16 lo = __float2bfloat16(s[i] - __bfloat162float(hi));
        size_t b = (size_t)r * (3 * K);
        d[b + k] = hi; d[b + K + k] = hi; d[b + 2 * K + k] = lo;
    }
}
__device__ __forceinline__ void packW2(const float* s, __nv_bfloat16* d, int n,
                                       int tid0, int stride)
{   // W_hh [hi|lo], K=1024
    for (int i = tid0; i < n; i += stride) {
        int r = i >> 10, k = i & 1023;
        __nv_bfloat16 hi = __float2bfloat16(s[i]);
        __nv_bfloat16 lo = __float2bfloat16(s[i] - __bfloat162float(hi));
        size_t b = (size_t)r * 2048;
        d[b + k] = hi; d[b + 1024 + k] = lo;
    }
}

__global__ void prep_w(const float* __restrict__ W_hh0, const float* __restrict__ W_hh1,
                       const float* __restrict__ W_ih0, const float* __restrict__ W_ih1,
                       __nv_bfloat16* __restrict__ wh0, __nv_bfloat16* __restrict__ wh1,
                       __nv_bfloat16* __restrict__ w0p, __nv_bfloat16* __restrict__ w1p)
{
    int tid0 = blockIdx.x * blockDim.x + threadIdx.x;
    int stride = gridDim.x * blockDim.x;
    packW2(W_hh0, wh0, G3_ * H_, tid0, stride);
    packW2(W_hh1, wh1, G3_ * H_, tid0, stride);
    packB3(W_ih0, w0p, G3_ * IN_, IN_, tid0, stride);
    packB3(W_ih1, w1p, G3_ * H_, H_, tid0, stride);
}

__global__ void prep_x(const float* __restrict__ x, __nv_bfloat16* __restrict__ xp)
{   // A-side [hi|lo|hi], K=IN_
    int tid0 = blockIdx.x * blockDim.x + threadIdx.x;
    int stride = gridDim.x * blockDim.x;
    for (int i = tid0; i < M_ * IN_; i += stride) {
        int r = i / IN_, k = i % IN_;
        __nv_bfloat16 hi = __float2bfloat16(x[i]);
        __nv_bfloat16 lo = __float2bfloat16(x[i] - __bfloat162float(hi));
        size_t b = (size_t)r * (3 * IN_);
        xp[b + k] = hi; xp[b + IN_ + k] = lo; xp[b + 2 * IN_ + k] = hi;
    }
}

// -------- input-projection GEMM: C[M][3072] = A[M][K3] * Bm[3072][K3]^T + bias
__global__ void __launch_bounds__(256)
gemm_mma(const __nv_bfloat16* __restrict__ A, const __nv_bfloat16* __restrict__ Bm,
         const float* __restrict__ bias, float* __restrict__ C, int K3)
{
    __shared__ __nv_bfloat16 As[2][128][24];
    __shared__ __nv_bfloat16 Bs[2][64][24];
    const int n0 = blockIdx.x * 64, m0 = blockIdx.y * 128;
    const int tid = threadIdx.x, w = tid >> 5, lane = tid & 31;
    const int mw = w >> 1, nw = w & 1, g = lane >> 2, q = lane & 3;

    float acc[2][4][4];
#pragma unroll
    for (int i=0;i<2;i++) for (int j=0;j<4;j++) for (int e=0;e<4;e++) acc[i][j][e]=0.f;

    const int steps = K3 / 16;
    const int arow = tid >> 1, ah = tid & 1;
    const bool bl = tid < 128;
    uint4 ra, rb;
    ra = *(const uint4*)(A + (size_t)(m0+arow)*K3 + ah*8);
    if (bl) rb = *(const uint4*)(Bm + (size_t)(n0+arow)*K3 + ah*8);
    *(uint4*)&As[0][arow][ah*8] = ra;
    if (bl) *(uint4*)&Bs[0][arow][ah*8] = rb;
    __syncthreads();

    for (int c = 0; c < steps; c++) {
        if (c+1 < steps) {
            int kb = (c+1)*16;
            ra = *(const uint4*)(A + (size_t)(m0+arow)*K3 + kb + ah*8);
            if (bl) rb = *(const uint4*)(Bm + (size_t)(n0+arow)*K3 + kb + ah*8);
        }
        const int p = c & 1;
        unsigned bf[4][2];
#pragma unroll
        for (int j=0;j<4;j++) {
            int col = nw*32 + j*8 + g;
            bf[j][0] = *(const unsigned*)&Bs[p][col][q*2];
            bf[j][1] = *(const unsigned*)&Bs[p][col][q*2+8];
        }
#pragma unroll
        for (int i=0;i<2;i++) {
            int r = mw*32 + i*16 + g;
            unsigned a[4];
            a[0] = *(const unsigned*)&As[p][r][q*2];
            a[1] = *(const unsigned*)&As[p][r+8][q*2];
            a[2] = *(const unsigned*)&As[p][r][q*2+8];
            a[3] = *(const unsigned*)&As[p][r+8][q*2+8];
#pragma unroll
            for (int j=0;j<4;j++) mma_bf16(acc[i][j], a, bf[j]);
        }
        if (c+1 < steps) {
            *(uint4*)&As[(c+1)&1][arow][ah*8] = ra;
            if (bl) *(uint4*)&Bs[(c+1)&1][arow][ah*8] = rb;
            __syncthreads();
        }
    }
#pragma unroll
    for (int i=0;i<2;i++) {
        int row = m0 + mw*32 + i*16 + g;
#pragma unroll
        for (int j=0;j<4;j++) {
            int col = n0 + nw*32 + j*8 + q*2;
            float b0 = bias[col], b1 = bias[col+1];
            *(float2*)(C + (size_t)row*G3_ + col)     = make_float2(acc[i][j][0]+b0, acc[i][j][1]+b1);
            *(float2*)(C + (size_t)(row+8)*G3_ + col) = make_float2(acc[i][j][2]+b0, acc[i][j][3]+b1);
        }
    }
}

// -------- persistent recurrence: W tile resident in smem --------
__global__ void __launch_bounds__(256, 1)
gru_rec(const __nv_bfloat16* __restrict__ Wp, const float* __restrict__ b_hh,
        const float* __restrict__ xg, __nv_bfloat16* __restrict__ hp,
        float* __restrict__ hf, float* __restrict__ hg,
        __nv_bfloat16* __restrict__ yp)
{
    extern __shared__ __nv_bfloat16 smb[];
    __nv_bfloat16* Ws = smb;                    // 32 x WSTR (hi 0..1023, lo 1024..2047)
    __nv_bfloat16* Ab = smb + 32 * WSTR;        // 2 x 64 x ASTR (hi 0..127, lo 128..255)

    const int cta = blockIdx.x, tid = threadIdx.x;
    const int lane = tid & 31, w = tid >> 5;
    const int mw = w >> 1, nw = w & 1, g = lane >> 2, q = lane & 3;
    const int n0 = cta * 32;

    // one-time W tile load: 32 rows x 2048 bf16
#pragma unroll 4
    for (int i = tid; i < 32 * 256; i += 256) {
        int r = i >> 8, c8 = i & 255;
        uint4 v = __ldg((const uint4*)(Wp + (size_t)(n0 + r) * 2048 + c8 * 8));
        *(uint4*)(Ws + r * WSTR + c8 * 8) = v;
    }

    for (int i = cta * 256 + tid; i < B_ * H_; i += RECG * 256) {
        ((unsigned*)hp)[i] = 0u; hf[i] = 0.f;
    }
    grid_barrier();

    const int sr  = tid >> 5;          // staging: row per warp-slot = idx>>5
    const int sc8 = tid & 31;

    for (int t = 0; t < T_; t++) {
        // ---- stage chunk 0 (k 0..127 hi + lo), double-buffered over 8 chunks
        uint4 pr[8];
#pragma unroll
        for (int i2 = 0; i2 < 8; i2++) {
            int r = sr + i2 * 8;
            size_t src = (size_t)r * 2048 + (sc8 >> 4) * 1024 + (sc8 & 15) * 8;
            pr[i2] = __ldcg((const uint4*)(hp + src));
        }
#pragma unroll
        for (int i2 = 0; i2 < 8; i2++) {
            int r = sr + i2 * 8;
            *(uint4*)(Ab + r * ASTR + sc8 * 8) = pr[i2];
        }
        __syncthreads();

        float accA[2][4], accB[2][4];
#pragma unroll
        for (int j = 0; j < 2; j++)
#pragma unroll
            for (int e = 0; e < 4; e++) { accA[j][e] = 0.f; accB[j][e] = 0.f; }

        for (int kc = 0; kc < 8; kc++) {
            if (kc + 1 < 8) {
#pragma unroll
                for (int i2 = 0; i2 < 8; i2++) {
                    int r = sr + i2 * 8;
                    size_t src = (size_t)r * 2048 + (sc8 >> 4) * 1024 + (kc + 1) * 128 + (sc8 & 15) * 8;
                    pr[i2] = __ldcg((const uint4*)(hp + src));
                }
            }
            const __nv_bfloat16* Ap = Ab + (kc & 1) * 64 * ASTR + (mw * 16 + g) * ASTR;
#pragma unroll
            for (int kk = 0; kk < 8; kk++) {
                const int kt = kc * 8 + kk;
                const __nv_bfloat16* ap = Ap + kk * 16 + q * 2;
                unsigned ah[4], al[4];
                ah[0] = *(const unsigned*)ap;
                ah[1] = *(const unsigned*)(ap + 8 * ASTR);
                ah[2] = *(const unsigned*)(ap + 8);
                ah[3] = *(const unsigned*)(ap + 8 * ASTR + 8);
                al[0] = *(const unsigned*)(ap + 128);
                al[1] = *(const unsigned*)(ap + 8 * ASTR + 128);
                al[2] = *(const unsigned*)(ap + 136);
                al[3] = *(const unsigned*)(ap + 8 * ASTR + 136);
#pragma unroll
                for (int j = 0; j < 2; j++) {
                    const __nv_bfloat16* bp = Ws + (size_t)(nw * 16 + j * 8 + g) * WSTR + kt * 16 + q * 2;
                    unsigned bh[2], blo[2];
                    bh[0]  = *(const unsigned*)bp;
                    bh[1]  = *(const unsigned*)(bp + 8);
                    blo[0] = *(const unsigned*)(bp + 1024);
                    blo[1] = *(const unsigned*)(bp + 1032);
                    mma_bf16(accA[j], ah, bh);
                    mma_bf16(accB[j], al, bh);
                    mma_bf16(accB[j], ah, blo);
                }
            }
            if (kc + 1 < 8) {
                __nv_bfloat16* dst = Ab + ((kc + 1) & 1) * 64 * ASTR;
#pragma unroll
                for (int i2 = 0; i2 < 8; i2++) {
                    int r = sr + i2 * 8;
                    *(uint4*)(dst + r * ASTR + sc8 * 8) = pr[i2];
                }
                __syncthreads();
            }
        }

        // ---- write hg tile
#pragma unroll
        for (int j = 0; j < 2; j++) {
            int row = mw * 16 + g, col = n0 + nw * 16 + j * 8 + q * 2;
            *(float2*)(hg + (size_t)row * G3_ + col) =
                make_float2(accA[j][0] + accB[j][0], accA[j][1] + accB[j][1]);
            *(float2*)(hg + (size_t)(row + 8) * G3_ + col) =
                make_float2(accA[j][2] + accB[j][2], accA[j][3] + accB[j][3]);
        }
        grid_barrier();

        // ---- gates
        const float* hin = hf + (t & 1) * (B_ * H_);
        float* hout      = hf + ((t + 1) & 1) * (B_ * H_);
        for (int e = cta * 256 + tid; e < B_ * H_ / 2; e += RECG * 256) {
            int b = e >> 9, jj = (e & 511) * 2;
            size_t gb = (size_t)b * G3_;
            float2 hr = __ldcg((const float2*)(hg + gb + jj));
            float2 hz = __ldcg((const float2*)(hg + gb + H_ + jj));
            float2 hn = __ldcg((const float2*)(hg + gb + 2 * H_ + jj));
            const float* xp2 = xg + ((size_t)b * T_ + t) * G3_;
            float2 xr = *(const float2*)(xp2 + jj);
            float2 xz = *(const float2*)(xp2 + H_ + jj);
            float2 xn = *(const float2*)(xp2 + 2 * H_ + jj);
            float2 br = *(const float2*)(b_hh + jj);
            float2 bz = *(const float2*)(b_hh + H_ + jj);
            float2 bn = *(const float2*)(b_hh + 2 * H_ + jj);
            float2 hv = __ldcg((const float2*)(hin + (size_t)b * H_ + jj));
            float ho[2];
            float xrv[2]={xr.x,xr.y}, xzv[2]={xz.x,xz.y}, xnv[2]={xn.x,xn.y};
            float hrv[2]={hr.x+br.x,hr.y+br.y}, hzv[2]={hz.x+bz.x,hz.y+bz.y};
            float hnv[2]={hn.x+bn.x,hn.y+bn.y}, hpv[2]={hv.x,hv.y};
#pragma unroll
            for (int k = 0; k < 2; k++) {
                float r = 1.f / (1.f + expf(-(xrv[k] + hrv[k])));
                float z = 1.f / (1.f + expf(-(xzv[k] + hzv[k])));
                float n = tanhf(xnv[k] + r * hnv[k]);
                ho[k] = (1.f - z) * n + z * hpv[k];
            }
            *(float2*)(hout + (size_t)b * H_ + jj) = make_float2(ho[0], ho[1]);
            __nv_bfloat162 hi2, lo2;
            hi2.x = __float2bfloat16(ho[0]); hi2.y = __float2bfloat16(ho[1]);
            lo2.x = __float2bfloat16(ho[0] - __bfloat162float(hi2.x));
            lo2.y = __float2bfloat16(ho[1] - __bfloat162float(hi2.y));
            *(__nv_bfloat162*)(hp + (size_t)b * 2048 + jj)        = hi2;
            *(__nv_bfloat162*)(hp + (size_t)b * 2048 + 1024 + jj) = lo2;
            if (yp) {
                size_t yr = ((size_t)b * T_ + t) * 3072;
                *(__nv_bfloat162*)(yp + yr + jj)        = hi2;
                *(__nv_bfloat162*)(yp + yr + 1024 + jj) = lo2;
                *(__nv_bfloat162*)(yp + yr + 2048 + jj) = hi2;
            }
        }
        grid_barrier();
    }
}

// -------- final fc --------
__global__ void fc_kernel(const float* __restrict__ h, const float* __restrict__ Wfc,
                          const float* __restrict__ bfc, float* __restrict__ out)
{
    int b = blockIdx.x;
    float s = 0.f;
    for (int j = threadIdx.x; j < H_; j += blockDim.x) s += h[b*H_+j] * Wfc[j];
    __shared__ float red[256];
    red[threadIdx.x] = s; __syncthreads();
    for (int o = 128; o > 0; o >>= 1) {
        if (threadIdx.x < o) red[threadIdx.x] += red[threadIdx.x+o];
        __syncthreads();
    }
    if (threadIdx.x == 0) out[b] = red[0] + bfc[0];
}

// -------- launch --------
extern "C" void kernel_launch(void* const* d_in, const int* in_sizes, int n_in,
                              void* d_out, int out_size)
{
    const float* x     = (const float*)d_in[0];
    const float* W_ih0 = (const float*)d_in[1];
    const float* W_hh0 = (const float*)d_in[2];
    const float* b_ih0 = (const float*)d_in[3];
    const float* b_hh0 = (const float*)d_in[4];
    const float* W_ih1 = (const float*)d_in[5];
    const float* W_hh1 = (const float*)d_in[6];
    const float* b_ih1 = (const float*)d_in[7];
    const float* b_hh1 = (const float*)d_in[8];
    const float* W_fc  = (const float*)d_in[9];
    const float* b_fc  = (const float*)d_in[10];
    float* out = (float*)d_out;

    float *xg, *hf, *hg;
    __nv_bfloat16 *xp, *yp, *w0p, *w1p, *wh0, *wh1, *hp;
    cudaGetSymbolAddress((void**)&xg,  g_xg);
    cudaGetSymbolAddress((void**)&xp,  g_xp);
    cudaGetSymbolAddress((void**)&yp,  g_yp);
    cudaGetSymbolAddress((void**)&w0p, g_w0p);
    cudaGetSymbolAddress((void**)&w1p, g_w1p);
    cudaGetSymbolAddress((void**)&wh0, g_wh0);
    cudaGetSymbolAddress((void**)&wh1, g_wh1);
    cudaGetSymbolAddress((void**)&hp,  g_hp);
    cudaGetSymbolAddress((void**)&hf,  g_hf);
    cudaGetSymbolAddress((void**)&hg,  g_hg);

    static int smem_set = 0;
    if (!smem_set) {
        cudaFuncSetAttribute(gru_rec, cudaFuncAttributeMaxDynamicSharedMemorySize, REC_SMEM);
        smem_set = 1;
    }

    prep_w<<<1024, 256>>>(W_hh0, W_hh1, W_ih0, W_ih1, wh0, wh1, w0p, w1p);
    prep_x<<<512, 256>>>(x, xp);

    gemm_mma<<<dim3(48, 256), 256>>>(xp, w0p, b_ih0, xg, 3*IN_);
    gru_rec<<<RECG, 256, REC_SMEM>>>(wh0, b_hh0, xg, hp, hf, hg, yp);
    gemm_mma<<<dim3(48, 256), 256>>>(yp, w1p, b_ih1, xg, 3*H_);
    gru_rec<<<RECG, 256, REC_SMEM>>>(wh1, b_hh1, xg, hp, hf, hg, nullptr);

    fc_kernel<<<B_, 256>>>(hf, W_fc, b_fc, out);   // final h in buffer 0
}